// round 1
// baseline (speedup 1.0000x reference)
#include <cuda_runtime.h>
#include <cuda_bf16.h>
#include <math.h>
#include <stdint.h>

// ---------------- Model constants ----------------
#define BATCH 4
#define SEQ   4096
#define DMODEL 768
#define NHEAD 12
#define DHEAD 64
#define BLKS  64          // block size (BS)
#define NLAYER 2
#define NRAND 3
#define FFDIM 3072
#define NBLK  64          // SEQ / BLKS
#define NSEL  8           // 2 global + 3 window + 3 random
#define NTOK  (BATCH*SEQ) // 16384

// ---------------- Scratch (device globals; no allocation allowed) ----------------
__device__ float g_h[NTOK * DMODEL];          // hidden states      ~50 MB
__device__ float g_qkv[NTOK * 3 * DMODEL];    // qkv activations    ~151 MB
__device__ float g_o[NTOK * DMODEL];          // attn out / ff2 out ~50 MB
__device__ float g_tmp[NTOK * FFDIM];         // proj / ff1 out     ~201 MB

// ---------------- Helpers ----------------
__device__ __forceinline__ float gelu_tanh(float x) {
    float x3 = x * x * x;
    return 0.5f * x * (1.0f + tanhf(0.7978845608028654f * (x + 0.044715f * x3)));
}

// block-wide reduce of two sums over 256 threads
__device__ __forceinline__ void block_reduce2(float& s1, float& s2) {
    __shared__ float sh1[8], sh2[8];
    int lane = threadIdx.x & 31, w = threadIdx.x >> 5;
    #pragma unroll
    for (int o = 16; o > 0; o >>= 1) {
        s1 += __shfl_down_sync(0xffffffffu, s1, o);
        s2 += __shfl_down_sync(0xffffffffu, s2, o);
    }
    if (lane == 0) { sh1[w] = s1; sh2[w] = s2; }
    __syncthreads();
    if (w == 0) {
        s1 = (lane < 8) ? sh1[lane] : 0.f;
        s2 = (lane < 8) ? sh2[lane] : 0.f;
        #pragma unroll
        for (int o = 4; o > 0; o >>= 1) {
            s1 += __shfl_down_sync(0xffffffffu, s1, o);
            s2 += __shfl_down_sync(0xffffffffu, s2, o);
        }
        if (lane == 0) { sh1[0] = s1; sh2[0] = s2; }
    }
    __syncthreads();
    s1 = sh1[0]; s2 = sh2[0];
}

// ---------------- Embedding + LayerNorm ----------------
// one block per token, 256 threads, 3 elems/thread
__global__ void embed_ln_kernel(const int* __restrict__ ids,
                                const float* __restrict__ emb,
                                const float* __restrict__ pos,
                                const float* __restrict__ g,
                                const float* __restrict__ b,
                                float* __restrict__ out) {
    int tok = blockIdx.x;
    int s = tok % SEQ;
    int id = ids[tok];
    const float* erow = emb + (size_t)id * DMODEL;
    const float* prow = pos + (size_t)s * DMODEL;
    float v[3];
    float sum = 0.f, sumsq = 0.f;
    #pragma unroll
    for (int i = 0; i < 3; i++) {
        int d = threadIdx.x + i * 256;
        v[i] = erow[d] + prow[d];
        sum += v[i]; sumsq += v[i] * v[i];
    }
    block_reduce2(sum, sumsq);
    float mean = sum * (1.0f / DMODEL);
    float var = sumsq * (1.0f / DMODEL) - mean * mean;
    float rstd = rsqrtf(var + 1e-12f);
    float* orow = out + (size_t)tok * DMODEL;
    #pragma unroll
    for (int i = 0; i < 3; i++) {
        int d = threadIdx.x + i * 256;
        orow[d] = (v[i] - mean) * rstd * g[d] + b[d];
    }
}

// ---------------- Residual + LayerNorm (in place on h) ----------------
__global__ void ln_residual_kernel(float* __restrict__ h,
                                   const float* __restrict__ x,
                                   const float* __restrict__ g,
                                   const float* __restrict__ b) {
    int tok = blockIdx.x;
    float* hrow = h + (size_t)tok * DMODEL;
    const float* xrow = x + (size_t)tok * DMODEL;
    float v[3];
    float sum = 0.f, sumsq = 0.f;
    #pragma unroll
    for (int i = 0; i < 3; i++) {
        int d = threadIdx.x + i * 256;
        v[i] = hrow[d] + xrow[d];
        sum += v[i]; sumsq += v[i] * v[i];
    }
    block_reduce2(sum, sumsq);
    float mean = sum * (1.0f / DMODEL);
    float var = sumsq * (1.0f / DMODEL) - mean * mean;
    float rstd = rsqrtf(var + 1e-12f);
    #pragma unroll
    for (int i = 0; i < 3; i++) {
        int d = threadIdx.x + i * 256;
        hrow[d] = (v[i] - mean) * rstd * g[d] + b[d];
    }
}

// ---------------- SGEMM: C = A[MxK] * B[KxN] + bias, optional GELU ----------------
// 128x128 tile, BK=8, 256 threads, 8x8 per thread. All dims divisible.
template <bool GELU>
__global__ __launch_bounds__(256) void sgemm_bias_kernel(
    const float* __restrict__ A, const float* __restrict__ B,
    const float* __restrict__ bias, float* __restrict__ C,
    int M, int N, int K) {
    __shared__ float As[8][128];
    __shared__ float Bs[8][128];

    const int cRow = blockIdx.y;
    const int cCol = blockIdx.x;
    const int tid = threadIdx.x;
    const int threadRow = tid / 16;   // 0..15
    const int threadCol = tid % 16;   // 0..15

    const float* Ag = A + (size_t)cRow * 128 * K;
    const float* Bg = B + (size_t)cCol * 128;
    float* Cg = C + (size_t)cRow * 128 * N + (size_t)cCol * 128;

    const int innerRowA = tid / 2;          // 0..127
    const int innerColA = (tid % 2) * 4;    // 0 or 4
    const int innerRowB = tid / 32;         // 0..7
    const int innerColB = (tid % 32) * 4;   // 0..124

    float acc[8][8];
    #pragma unroll
    for (int i = 0; i < 8; i++)
        #pragma unroll
        for (int j = 0; j < 8; j++) acc[i][j] = 0.f;

    for (int kb = 0; kb < K; kb += 8) {
        float4 a = *reinterpret_cast<const float4*>(&Ag[(size_t)innerRowA * K + innerColA]);
        As[innerColA + 0][innerRowA] = a.x;
        As[innerColA + 1][innerRowA] = a.y;
        As[innerColA + 2][innerRowA] = a.z;
        As[innerColA + 3][innerRowA] = a.w;
        float4 bv = *reinterpret_cast<const float4*>(&Bg[(size_t)innerRowB * N + innerColB]);
        *reinterpret_cast<float4*>(&Bs[innerRowB][innerColB]) = bv;
        __syncthreads();
        Ag += 8;
        Bg += (size_t)8 * N;
        #pragma unroll
        for (int k = 0; k < 8; k++) {
            float regM[8], regN[8];
            #pragma unroll
            for (int i = 0; i < 8; i++) regM[i] = As[k][threadRow * 8 + i];
            #pragma unroll
            for (int j = 0; j < 8; j++) regN[j] = Bs[k][threadCol * 8 + j];
            #pragma unroll
            for (int i = 0; i < 8; i++)
                #pragma unroll
                for (int j = 0; j < 8; j++)
                    acc[i][j] = fmaf(regM[i], regN[j], acc[i][j]);
        }
        __syncthreads();
    }

    #pragma unroll
    for (int i = 0; i < 8; i++) {
        #pragma unroll
        for (int j = 0; j < 8; j++) {
            int gcol = cCol * 128 + threadCol * 8 + j;
            float v = acc[i][j] + bias[gcol];
            if (GELU) v = gelu_tanh(v);
            Cg[(size_t)(threadRow * 8 + i) * N + threadCol * 8 + j] = v;
        }
    }
}

// ---------------- Block-sparse attention ----------------
// grid (NBLK, NHEAD, BATCH), 256 threads.
// Each quad of 4 threads owns one query row (64 rows); each thread owns 16 of 64 dims.
__device__ __forceinline__ int sel_block(int i, int nb, const int* __restrict__ rand_idx) {
    switch (i) {
        case 0: return 0;
        case 1: return (nb + NBLK - 1) % NBLK;
        case 2: return nb;
        case 3: return (nb + 1) % NBLK;
        case 4: return NBLK - 1;
        default: return rand_idx[nb * NRAND + (i - 5)];
    }
}

__global__ __launch_bounds__(256) void attn_kernel(
    const float* __restrict__ qkv, const int* __restrict__ amask,
    const int* __restrict__ rand_idx, float* __restrict__ o) {
    const int nb = blockIdx.x;
    const int h  = blockIdx.y;
    const int b  = blockIdx.z;
    const int tid = threadIdx.x;
    const int qrow = tid >> 2;        // 0..63
    const int quad = tid & 3;         // 0..3
    const int off = quad * 16;

    __shared__ float Ks[64][64];
    __shared__ float Vs[64][64];
    __shared__ float kb_bias[64];

    const float scale = 0.125f; // 1/sqrt(64)
    const size_t q_tok = (size_t)b * SEQ + nb * BLKS + qrow;

    float qreg[16];
    {
        const float* qptr = qkv + q_tok * (3 * DMODEL) + h * DHEAD + off;
        #pragma unroll
        for (int j = 0; j < 16; j += 4) {
            float4 t = *reinterpret_cast<const float4*>(qptr + j);
            qreg[j + 0] = t.x * scale; qreg[j + 1] = t.y * scale;
            qreg[j + 2] = t.z * scale; qreg[j + 3] = t.w * scale;
        }
    }

    float acc[16];
    #pragma unroll
    for (int j = 0; j < 16; j++) acc[j] = 0.f;
    float mval = -INFINITY, lval = 0.f;

    for (int i = 0; i < NSEL; i++) {
        int sb = sel_block(i, nb, rand_idx);
        size_t base_tok = (size_t)b * SEQ + sb * BLKS;
        // cooperative load of K and V blocks: thread loads row qrow, cols off..off+15
        {
            const float* kptr = qkv + (base_tok + qrow) * (3 * DMODEL) + DMODEL + h * DHEAD + off;
            const float* vptr = qkv + (base_tok + qrow) * (3 * DMODEL) + 2 * DMODEL + h * DHEAD + off;
            #pragma unroll
            for (int j = 0; j < 16; j += 4) {
                *reinterpret_cast<float4*>(&Ks[qrow][off + j]) =
                    *reinterpret_cast<const float4*>(kptr + j);
                *reinterpret_cast<float4*>(&Vs[qrow][off + j]) =
                    *reinterpret_cast<const float4*>(vptr + j);
            }
        }
        if (tid < 64)
            kb_bias[tid] = (amask[b * SEQ + sb * BLKS + tid] > 0) ? 0.f : -1e9f;
        __syncthreads();

        #pragma unroll 4
        for (int k = 0; k < BLKS; k++) {
            float s = 0.f;
            #pragma unroll
            for (int j = 0; j < 16; j++) s = fmaf(qreg[j], Ks[k][off + j], s);
            s += __shfl_xor_sync(0xffffffffu, s, 1);
            s += __shfl_xor_sync(0xffffffffu, s, 2);
            s += kb_bias[k];
            float mnew = fmaxf(mval, s);
            float corr = __expf(mval - mnew);   // exp(-inf)=0 handles first iter
            float p = __expf(s - mnew);
            lval = lval * corr + p;
            #pragma unroll
            for (int j = 0; j < 16; j++)
                acc[j] = acc[j] * corr + p * Vs[k][off + j];
            mval = mnew;
        }
        __syncthreads();
    }

    float inv = 1.0f / lval;
    float* optr = o + q_tok * DMODEL + h * DHEAD + off;
    #pragma unroll
    for (int j = 0; j < 16; j += 4) {
        float4 t;
        t.x = acc[j + 0] * inv; t.y = acc[j + 1] * inv;
        t.z = acc[j + 2] * inv; t.w = acc[j + 3] * inv;
        *reinterpret_cast<float4*>(optr + j) = t;
    }
}

// ---------------- Pooler + classifier (probs) ----------------
// one block per batch element
__global__ void pooler_classify_kernel(const float* __restrict__ h,
                                       const float* __restrict__ Wp,
                                       const float* __restrict__ bp,
                                       const float* __restrict__ Wc,
                                       const float* __restrict__ bc,
                                       float* __restrict__ out_probs) {
    int b = blockIdx.x;
    __shared__ float pooled[DMODEL];
    const float* hrow = h + (size_t)b * SEQ * DMODEL;  // token (b, 0)
    for (int d = threadIdx.x; d < DMODEL; d += blockDim.x) {
        float s = bp[d];
        for (int k = 0; k < DMODEL; k++) s = fmaf(hrow[k], Wp[(size_t)k * DMODEL + d], s);
        pooled[d] = tanhf(s);
    }
    __syncthreads();
    if (threadIdx.x == 0) {
        float l0 = bc[0], l1 = bc[1];
        for (int k = 0; k < DMODEL; k++) {
            l0 = fmaf(pooled[k], Wc[2 * k + 0], l0);
            l1 = fmaf(pooled[k], Wc[2 * k + 1], l1);
        }
        float m = fmaxf(l0, l1);
        float e0 = expf(l0 - m), e1 = expf(l1 - m);
        float inv = 1.0f / (e0 + e1);
        out_probs[b * 2 + 0] = e0 * inv;
        out_probs[b * 2 + 1] = e1 * inv;
    }
}

// loss = -mean_b log_softmax(probs)[b, label[b]]  (double softmax, faithful to ref)
__global__ void loss_kernel(const float* __restrict__ probs,
                            const int* __restrict__ label,
                            float* __restrict__ out_loss) {
    if (threadIdx.x == 0 && blockIdx.x == 0) {
        float acc = 0.f;
        for (int b = 0; b < BATCH; b++) {
            float p0 = probs[2 * b], p1 = probs[2 * b + 1];
            float m = fmaxf(p0, p1);
            float lse = m + logf(expf(p0 - m) + expf(p1 - m));
            float pl = (label[b] == 0) ? p0 : p1;
            acc += -(pl - lse);
        }
        out_loss[0] = acc * (1.0f / BATCH);
    }
}

// ---------------- Host driver ----------------
static float* sym_addr(const void* sym) {
    void* p = nullptr;
    cudaGetSymbolAddress(&p, sym);
    return (float*)p;
}

extern "C" void kernel_launch(void* const* d_in, const int* in_sizes, int n_in,
                              void* d_out, int out_size) {
    const int*   input_ids = (const int*)d_in[0];
    const int*   amask     = (const int*)d_in[1];
    const int*   label     = (const int*)d_in[2];
    const int*   rand_idx  = (const int*)d_in[3];
    const float* emb       = (const float*)d_in[4];
    const float* pos_emb   = (const float*)d_in[5];
    const float* ln_emb_g  = (const float*)d_in[6];
    const float* ln_emb_b  = (const float*)d_in[7];
    const float* Wqkv      = (const float*)d_in[8];
    const float* bqkv      = (const float*)d_in[9];
    const float* Wo        = (const float*)d_in[10];
    const float* bo        = (const float*)d_in[11];
    const float* ln1_g     = (const float*)d_in[12];
    const float* ln1_b     = (const float*)d_in[13];
    const float* Wff1      = (const float*)d_in[14];
    const float* bff1      = (const float*)d_in[15];
    const float* Wff2      = (const float*)d_in[16];
    const float* bff2      = (const float*)d_in[17];
    const float* Wff2_end  = Wff2; (void)Wff2_end;
    const float* ln2_g     = (const float*)d_in[18];
    const float* ln2_b     = (const float*)d_in[19];
    const float* Wp        = (const float*)d_in[20];
    const float* bp        = (const float*)d_in[21];
    const float* Wc        = (const float*)d_in[22];
    const float* bc        = (const float*)d_in[23];

    float* h_buf   = sym_addr(g_h);
    float* qkv_buf = sym_addr(g_qkv);
    float* o_buf   = sym_addr(g_o);
    float* tmp_buf = sym_addr(g_tmp);

    float* out = (float*)d_out;

    // 1. embedding + LN
    embed_ln_kernel<<<NTOK, 256>>>(input_ids, emb, pos_emb, ln_emb_g, ln_emb_b, h_buf);

    for (int l = 0; l < NLAYER; l++) {
        const float* Wqkv_l = Wqkv + (size_t)l * DMODEL * 3 * DMODEL;
        const float* bqkv_l = bqkv + (size_t)l * 3 * DMODEL;
        const float* Wo_l   = Wo   + (size_t)l * DMODEL * DMODEL;
        const float* bo_l   = bo   + (size_t)l * DMODEL;
        const float* Wff1_l = Wff1 + (size_t)l * DMODEL * FFDIM;
        const float* bff1_l = bff1 + (size_t)l * FFDIM;
        const float* Wff2_l = Wff2 + (size_t)l * FFDIM * DMODEL;
        const float* bff2_l = bff2 + (size_t)l * DMODEL;

        // qkv = h @ Wqkv + bqkv   [16384 x 2304]
        {
            dim3 grid(3 * DMODEL / 128, NTOK / 128);
            sgemm_bias_kernel<false><<<grid, 256>>>(h_buf, Wqkv_l, bqkv_l, qkv_buf,
                                                    NTOK, 3 * DMODEL, DMODEL);
        }
        // sparse attention -> o_buf
        {
            dim3 grid(NBLK, NHEAD, BATCH);
            attn_kernel<<<grid, 256>>>(qkv_buf, amask, rand_idx, o_buf);
        }
        // tmp = o @ Wo + bo
        {
            dim3 grid(DMODEL / 128, NTOK / 128);
            sgemm_bias_kernel<false><<<grid, 256>>>(o_buf, Wo_l, bo_l, tmp_buf,
                                                    NTOK, DMODEL, DMODEL);
        }
        // h = LN(h + tmp)
        ln_residual_kernel<<<NTOK, 256>>>(h_buf, tmp_buf, ln1_g + l * DMODEL, ln1_b + l * DMODEL);
        // tmp = gelu(h @ Wff1 + bff1)  [16384 x 3072]
        {
            dim3 grid(FFDIM / 128, NTOK / 128);
            sgemm_bias_kernel<true><<<grid, 256>>>(h_buf, Wff1_l, bff1_l, tmp_buf,
                                                   NTOK, FFDIM, DMODEL);
        }
        // o = tmp @ Wff2 + bff2
        {
            dim3 grid(DMODEL / 128, NTOK / 128);
            sgemm_bias_kernel<false><<<grid, 256>>>(tmp_buf, Wff2_l, bff2_l, o_buf,
                                                    NTOK, DMODEL, FFDIM);
        }
        // h = LN(h + o)
        ln_residual_kernel<<<NTOK, 256>>>(h_buf, o_buf, ln2_g + l * DMODEL, ln2_b + l * DMODEL);
    }

    // pooler + classifier -> probs in out[0..7]
    pooler_classify_kernel<<<BATCH, 256>>>(h_buf, Wp, bp, Wc, bc, out);
    // loss -> out[8]
    loss_kernel<<<1, 32>>>(out, label, out + 8);
}

// round 2
// speedup vs baseline: 2.5897x; 2.5897x over previous
#include <cuda_runtime.h>
#include <cuda_bf16.h>
#include <math.h>
#include <stdint.h>

// ---------------- Model constants ----------------
#define BATCH 4
#define SEQ   4096
#define DMODEL 768
#define NHEAD 12
#define DHEAD 64
#define BLKS  64
#define NLAYER 2
#define NRAND 3
#define FFDIM 3072
#define NBLK  64
#define NSEL  8
#define NTOK  (BATCH*SEQ) // 16384

// weight bf16 buffer offsets (elements)
#define OFF_WQKV 0
#define SZ_WQKV  (NLAYER*DMODEL*3*DMODEL)        // 3,538,944
#define OFF_WO   (OFF_WQKV + SZ_WQKV)
#define SZ_WO    (NLAYER*DMODEL*DMODEL)          // 1,179,648
#define OFF_WFF1 (OFF_WO + SZ_WO)
#define SZ_WFF1  (NLAYER*DMODEL*FFDIM)           // 4,718,592
#define OFF_WFF2 (OFF_WFF1 + SZ_WFF1)
#define SZ_WFF2  (NLAYER*FFDIM*DMODEL)           // 4,718,592
#define WTOTAL   (OFF_WFF2 + SZ_WFF2)            // 14,155,776

// ---------------- Scratch (device globals) ----------------
__device__ float g_h[NTOK * DMODEL];
__device__ float g_qkv[NTOK * 3 * DMODEL];
__device__ float g_o[NTOK * DMODEL];
__device__ float g_tmp[NTOK * FFDIM];
__device__ __nv_bfloat16 g_a_hi[NTOK * FFDIM];
__device__ __nv_bfloat16 g_a_lo[NTOK * FFDIM];
__device__ __nv_bfloat16 g_w_hi[WTOTAL];
__device__ __nv_bfloat16 g_w_lo[WTOTAL];

// ---------------- Helpers ----------------
__device__ __forceinline__ float gelu_tanh(float x) {
    float x3 = x * x * x;
    return 0.5f * x * (1.0f + tanhf(0.7978845608028654f * (x + 0.044715f * x3)));
}

__device__ __forceinline__ void block_reduce2(float& s1, float& s2) {
    __shared__ float sh1[8], sh2[8];
    int lane = threadIdx.x & 31, w = threadIdx.x >> 5;
    #pragma unroll
    for (int o = 16; o > 0; o >>= 1) {
        s1 += __shfl_down_sync(0xffffffffu, s1, o);
        s2 += __shfl_down_sync(0xffffffffu, s2, o);
    }
    if (lane == 0) { sh1[w] = s1; sh2[w] = s2; }
    __syncthreads();
    if (w == 0) {
        s1 = (lane < 8) ? sh1[lane] : 0.f;
        s2 = (lane < 8) ? sh2[lane] : 0.f;
        #pragma unroll
        for (int o = 4; o > 0; o >>= 1) {
            s1 += __shfl_down_sync(0xffffffffu, s1, o);
            s2 += __shfl_down_sync(0xffffffffu, s2, o);
        }
        if (lane == 0) { sh1[0] = s1; sh2[0] = s2; }
    }
    __syncthreads();
    s1 = sh1[0]; s2 = sh2[0];
}

// ---------------- fp32 -> bf16 hi/lo split ----------------
__global__ void split_bf16_kernel(const float* __restrict__ x,
                                  __nv_bfloat16* __restrict__ hi,
                                  __nv_bfloat16* __restrict__ lo, int n4) {
    int i = blockIdx.x * blockDim.x + threadIdx.x;
    if (i >= n4) return;
    float4 v = reinterpret_cast<const float4*>(x)[i];
    __nv_bfloat16 h0 = __float2bfloat16(v.x);
    __nv_bfloat16 h1 = __float2bfloat16(v.y);
    __nv_bfloat16 h2 = __float2bfloat16(v.z);
    __nv_bfloat16 h3 = __float2bfloat16(v.w);
    __nv_bfloat16 l0 = __float2bfloat16(v.x - __bfloat162float(h0));
    __nv_bfloat16 l1 = __float2bfloat16(v.y - __bfloat162float(h1));
    __nv_bfloat16 l2 = __float2bfloat16(v.z - __bfloat162float(h2));
    __nv_bfloat16 l3 = __float2bfloat16(v.w - __bfloat162float(h3));
    __nv_bfloat162 hp0; hp0.x = h0; hp0.y = h1;
    __nv_bfloat162 hp1; hp1.x = h2; hp1.y = h3;
    __nv_bfloat162 lp0; lp0.x = l0; lp0.y = l1;
    __nv_bfloat162 lp1; lp1.x = l2; lp1.y = l3;
    reinterpret_cast<__nv_bfloat162*>(hi)[2 * i]     = hp0;
    reinterpret_cast<__nv_bfloat162*>(hi)[2 * i + 1] = hp1;
    reinterpret_cast<__nv_bfloat162*>(lo)[2 * i]     = lp0;
    reinterpret_cast<__nv_bfloat162*>(lo)[2 * i + 1] = lp1;
}

// ---------------- Embedding + LayerNorm ----------------
__global__ void embed_ln_kernel(const int* __restrict__ ids,
                                const float* __restrict__ emb,
                                const float* __restrict__ pos,
                                const float* __restrict__ g,
                                const float* __restrict__ b,
                                float* __restrict__ out) {
    int tok = blockIdx.x;
    int s = tok % SEQ;
    int id = ids[tok];
    const float* erow = emb + (size_t)id * DMODEL;
    const float* prow = pos + (size_t)s * DMODEL;
    float v[3];
    float sum = 0.f, sumsq = 0.f;
    #pragma unroll
    for (int i = 0; i < 3; i++) {
        int d = threadIdx.x + i * 256;
        v[i] = erow[d] + prow[d];
        sum += v[i]; sumsq += v[i] * v[i];
    }
    block_reduce2(sum, sumsq);
    float mean = sum * (1.0f / DMODEL);
    float var = sumsq * (1.0f / DMODEL) - mean * mean;
    float rstd = rsqrtf(var + 1e-12f);
    float* orow = out + (size_t)tok * DMODEL;
    #pragma unroll
    for (int i = 0; i < 3; i++) {
        int d = threadIdx.x + i * 256;
        orow[d] = (v[i] - mean) * rstd * g[d] + b[d];
    }
}

__global__ void ln_residual_kernel(float* __restrict__ h,
                                   const float* __restrict__ x,
                                   const float* __restrict__ g,
                                   const float* __restrict__ b) {
    int tok = blockIdx.x;
    float* hrow = h + (size_t)tok * DMODEL;
    const float* xrow = x + (size_t)tok * DMODEL;
    float v[3];
    float sum = 0.f, sumsq = 0.f;
    #pragma unroll
    for (int i = 0; i < 3; i++) {
        int d = threadIdx.x + i * 256;
        v[i] = hrow[d] + xrow[d];
        sum += v[i]; sumsq += v[i] * v[i];
    }
    block_reduce2(sum, sumsq);
    float mean = sum * (1.0f / DMODEL);
    float var = sumsq * (1.0f / DMODEL) - mean * mean;
    float rstd = rsqrtf(var + 1e-12f);
    #pragma unroll
    for (int i = 0; i < 3; i++) {
        int d = threadIdx.x + i * 256;
        hrow[d] = (v[i] - mean) * rstd * g[d] + b[d];
    }
}

// ---------------- Tensor-core GEMM (bf16 hi/lo split, fp32 accum) ----------------
// C[M,N] = A[M,K] @ B[K,N] + bias, optional GELU.
// CTA tile 128x128, BK=32, 256 threads (8 warps as 4Mx2N, warp tile 32x64).
#define BMT 128
#define BNT 128
#define BKT 32
#define SA  40   // padded A smem row (bf16 elems)
#define SB  136  // padded B smem row (bf16 elems)
#define ASTAGE (2 * BMT * SA)             // 10240 elems (2 planes)
#define BSTAGE (2 * BKT * SB)             // 8704 elems
#define STAGE_E (ASTAGE + BSTAGE)         // 18944 elems
#define GEMM_SMEM_BYTES (2 * STAGE_E * 2) // 75776 bytes

__device__ __forceinline__ uint32_t smem_u32(const void* p) {
    return (uint32_t)__cvta_generic_to_shared(p);
}
__device__ __forceinline__ void ldmatrix_x4(uint32_t* r, uint32_t addr) {
    asm volatile("ldmatrix.sync.aligned.m8n8.x4.shared.b16 {%0,%1,%2,%3}, [%4];"
                 : "=r"(r[0]), "=r"(r[1]), "=r"(r[2]), "=r"(r[3]) : "r"(addr));
}
__device__ __forceinline__ void ldmatrix_x4_t(uint32_t* r, uint32_t addr) {
    asm volatile("ldmatrix.sync.aligned.m8n8.x4.trans.shared.b16 {%0,%1,%2,%3}, [%4];"
                 : "=r"(r[0]), "=r"(r[1]), "=r"(r[2]), "=r"(r[3]) : "r"(addr));
}
__device__ __forceinline__ void mma_bf16(float* d, const uint32_t* a, const uint32_t* b) {
    asm volatile("mma.sync.aligned.m16n8k16.row.col.f32.bf16.bf16.f32 "
                 "{%0,%1,%2,%3}, {%4,%5,%6,%7}, {%8,%9}, {%0,%1,%2,%3};"
                 : "+f"(d[0]), "+f"(d[1]), "+f"(d[2]), "+f"(d[3])
                 : "r"(a[0]), "r"(a[1]), "r"(a[2]), "r"(a[3]), "r"(b[0]), "r"(b[1]));
}
__device__ __forceinline__ void cp_async16(void* dst, const void* src) {
    asm volatile("cp.async.cg.shared.global [%0], [%1], 16;"
                 :: "r"(smem_u32(dst)), "l"(src));
}

template <bool GELU>
__global__ __launch_bounds__(256, 1) void gemm_mma_kernel(
    const __nv_bfloat16* __restrict__ Ahi, const __nv_bfloat16* __restrict__ Alo,
    const __nv_bfloat16* __restrict__ Bhi, const __nv_bfloat16* __restrict__ Blo,
    const float* __restrict__ bias, float* __restrict__ C,
    int M, int N, int K)
{
    extern __shared__ __nv_bfloat16 smx[];
    const int tid = threadIdx.x;
    const int wid = tid >> 5;
    const int lane = tid & 31;
    const int m0 = blockIdx.y * BMT;
    const int n0 = blockIdx.x * BNT;
    const int wm0 = (wid & 3) * 32;
    const int wn0 = (wid >> 2) * 64;

    float acc[2][8][4];
    #pragma unroll
    for (int i = 0; i < 2; i++)
        #pragma unroll
        for (int j = 0; j < 8; j++)
            #pragma unroll
            for (int c = 0; c < 4; c++) acc[i][j][c] = 0.f;

    const int nk = K / BKT;

    // ---- stage loader ----
    auto load_stage = [&](int s, int k0) {
        __nv_bfloat16* base = smx + s * STAGE_E;
        // A: 2 planes x 128 rows x 4 chunks(16B) = 1024 chunks
        #pragma unroll
        for (int t = 0; t < 4; t++) {
            int idx = tid + t * 256;
            int plane = idx >> 9;
            int rem = idx & 511;
            int r = rem >> 2;
            int c = (rem & 3) << 3;
            const __nv_bfloat16* src =
                (plane ? Alo : Ahi) + (size_t)(m0 + r) * K + k0 + c;
            cp_async16(base + plane * (BMT * SA) + r * SA + c, src);
        }
        // B: 2 planes x 32 rows x 16 chunks = 1024 chunks
        __nv_bfloat16* bb = base + ASTAGE;
        #pragma unroll
        for (int t = 0; t < 4; t++) {
            int idx = tid + t * 256;
            int plane = idx >> 9;
            int rem = idx & 511;
            int r = rem >> 4;
            int c = (rem & 15) << 3;
            const __nv_bfloat16* src =
                (plane ? Blo : Bhi) + (size_t)(k0 + r) * N + n0 + c;
            cp_async16(bb + plane * (BKT * SB) + r * SB + c, src);
        }
    };

    load_stage(0, 0);
    asm volatile("cp.async.commit_group;");

    for (int kt = 0; kt < nk; kt++) {
        if (kt + 1 < nk) load_stage((kt + 1) & 1, (kt + 1) * BKT);
        asm volatile("cp.async.commit_group;");
        asm volatile("cp.async.wait_group 1;");
        __syncthreads();

        const int s = kt & 1;
        const __nv_bfloat16* As0 = smx + s * STAGE_E;
        const __nv_bfloat16* As1 = As0 + BMT * SA;
        const __nv_bfloat16* Bs0 = smx + s * STAGE_E + ASTAGE;
        const __nv_bfloat16* Bs1 = Bs0 + BKT * SB;

        #pragma unroll
        for (int kk = 0; kk < BKT; kk += 16) {
            uint32_t af[2][2][4];  // [plane][mi]
            #pragma unroll
            for (int mi = 0; mi < 2; mi++) {
                int row = wm0 + mi * 16 + (lane & 15);
                int col = kk + ((lane >> 4) << 3);
                ldmatrix_x4(af[0][mi], smem_u32(As0 + row * SA + col));
                ldmatrix_x4(af[1][mi], smem_u32(As1 + row * SA + col));
            }
            uint32_t bfr[2][4][4]; // [plane][ni]
            #pragma unroll
            for (int ni = 0; ni < 4; ni++) {
                int rr = kk + (lane & 15);
                int cc = wn0 + ni * 16 + ((lane >> 4) << 3);
                ldmatrix_x4_t(bfr[0][ni], smem_u32(Bs0 + rr * SB + cc));
                ldmatrix_x4_t(bfr[1][ni], smem_u32(Bs1 + rr * SB + cc));
            }
            #pragma unroll
            for (int mi = 0; mi < 2; mi++)
                #pragma unroll
                for (int ni = 0; ni < 4; ni++)
                    #pragma unroll
                    for (int hf = 0; hf < 2; hf++) {
                        int nj = ni * 2 + hf;
                        const uint32_t* bhi = &bfr[0][ni][hf * 2];
                        const uint32_t* blo = &bfr[1][ni][hf * 2];
                        mma_bf16(acc[mi][nj], af[0][mi], bhi);  // hi*hi
                        mma_bf16(acc[mi][nj], af[0][mi], blo);  // hi*lo
                        mma_bf16(acc[mi][nj], af[1][mi], bhi);  // lo*hi
                    }
        }
        __syncthreads();
    }

    // ---- epilogue ----
    #pragma unroll
    for (int mi = 0; mi < 2; mi++) {
        int gr = m0 + wm0 + mi * 16 + (lane >> 2);
        #pragma unroll
        for (int nj = 0; nj < 8; nj++) {
            int gc = n0 + wn0 + nj * 8 + (lane & 3) * 2;
            float b0 = bias[gc], b1 = bias[gc + 1];
            float v0 = acc[mi][nj][0] + b0;
            float v1 = acc[mi][nj][1] + b1;
            float v2 = acc[mi][nj][2] + b0;
            float v3 = acc[mi][nj][3] + b1;
            if (GELU) {
                v0 = gelu_tanh(v0); v1 = gelu_tanh(v1);
                v2 = gelu_tanh(v2); v3 = gelu_tanh(v3);
            }
            float2 p0; p0.x = v0; p0.y = v1;
            float2 p1; p1.x = v2; p1.y = v3;
            *reinterpret_cast<float2*>(&C[(size_t)gr * N + gc]) = p0;
            *reinterpret_cast<float2*>(&C[(size_t)(gr + 8) * N + gc]) = p1;
        }
    }
}

// ---------------- Block-sparse attention (fp32 SIMT) ----------------
__device__ __forceinline__ int sel_block(int i, int nb, const int* __restrict__ rand_idx) {
    switch (i) {
        case 0: return 0;
        case 1: return (nb + NBLK - 1) % NBLK;
        case 2: return nb;
        case 3: return (nb + 1) % NBLK;
        case 4: return NBLK - 1;
        default: return rand_idx[nb * NRAND + (i - 5)];
    }
}

__global__ __launch_bounds__(256) void attn_kernel(
    const float* __restrict__ qkv, const int* __restrict__ amask,
    const int* __restrict__ rand_idx, float* __restrict__ o) {
    const int nb = blockIdx.x;
    const int h  = blockIdx.y;
    const int b  = blockIdx.z;
    const int tid = threadIdx.x;
    const int qrow = tid >> 2;
    const int quad = tid & 3;
    const int off = quad * 16;

    __shared__ float Ks[64][64];
    __shared__ float Vs[64][64];
    __shared__ float kb_bias[64];

    const float scale = 0.125f;
    const size_t q_tok = (size_t)b * SEQ + nb * BLKS + qrow;

    float qreg[16];
    {
        const float* qptr = qkv + q_tok * (3 * DMODEL) + h * DHEAD + off;
        #pragma unroll
        for (int j = 0; j < 16; j += 4) {
            float4 t = *reinterpret_cast<const float4*>(qptr + j);
            qreg[j + 0] = t.x * scale; qreg[j + 1] = t.y * scale;
            qreg[j + 2] = t.z * scale; qreg[j + 3] = t.w * scale;
        }
    }

    float acc[16];
    #pragma unroll
    for (int j = 0; j < 16; j++) acc[j] = 0.f;
    float mval = -INFINITY, lval = 0.f;

    for (int i = 0; i < NSEL; i++) {
        int sb = sel_block(i, nb, rand_idx);
        size_t base_tok = (size_t)b * SEQ + sb * BLKS;
        {
            const float* kptr = qkv + (base_tok + qrow) * (3 * DMODEL) + DMODEL + h * DHEAD + off;
            const float* vptr = qkv + (base_tok + qrow) * (3 * DMODEL) + 2 * DMODEL + h * DHEAD + off;
            #pragma unroll
            for (int j = 0; j < 16; j += 4) {
                *reinterpret_cast<float4*>(&Ks[qrow][off + j]) =
                    *reinterpret_cast<const float4*>(kptr + j);
                *reinterpret_cast<float4*>(&Vs[qrow][off + j]) =
                    *reinterpret_cast<const float4*>(vptr + j);
            }
        }
        if (tid < 64)
            kb_bias[tid] = (amask[b * SEQ + sb * BLKS + tid] > 0) ? 0.f : -1e9f;
        __syncthreads();

        #pragma unroll 4
        for (int k = 0; k < BLKS; k++) {
            float s = 0.f;
            #pragma unroll
            for (int j = 0; j < 16; j++) s = fmaf(qreg[j], Ks[k][off + j], s);
            s += __shfl_xor_sync(0xffffffffu, s, 1);
            s += __shfl_xor_sync(0xffffffffu, s, 2);
            s += kb_bias[k];
            float mnew = fmaxf(mval, s);
            float corr = __expf(mval - mnew);
            float p = __expf(s - mnew);
            lval = lval * corr + p;
            #pragma unroll
            for (int j = 0; j < 16; j++)
                acc[j] = acc[j] * corr + p * Vs[k][off + j];
            mval = mnew;
        }
        __syncthreads();
    }

    float inv = 1.0f / lval;
    float* optr = o + q_tok * DMODEL + h * DHEAD + off;
    #pragma unroll
    for (int j = 0; j < 16; j += 4) {
        float4 t;
        t.x = acc[j + 0] * inv; t.y = acc[j + 1] * inv;
        t.z = acc[j + 2] * inv; t.w = acc[j + 3] * inv;
        *reinterpret_cast<float4*>(optr + j) = t;
    }
}

// ---------------- Pooler + classifier ----------------
__global__ void pooler_classify_kernel(const float* __restrict__ h,
                                       const float* __restrict__ Wp,
                                       const float* __restrict__ bp,
                                       const float* __restrict__ Wc,
                                       const float* __restrict__ bc,
                                       float* __restrict__ out_probs) {
    int b = blockIdx.x;
    __shared__ float pooled[DMODEL];
    const float* hrow = h + (size_t)b * SEQ * DMODEL;
    for (int d = threadIdx.x; d < DMODEL; d += blockDim.x) {
        float s = bp[d];
        for (int k = 0; k < DMODEL; k++) s = fmaf(hrow[k], Wp[(size_t)k * DMODEL + d], s);
        pooled[d] = tanhf(s);
    }
    __syncthreads();
    if (threadIdx.x == 0) {
        float l0 = bc[0], l1 = bc[1];
        for (int k = 0; k < DMODEL; k++) {
            l0 = fmaf(pooled[k], Wc[2 * k + 0], l0);
            l1 = fmaf(pooled[k], Wc[2 * k + 1], l1);
        }
        float m = fmaxf(l0, l1);
        float e0 = expf(l0 - m), e1 = expf(l1 - m);
        float inv = 1.0f / (e0 + e1);
        out_probs[b * 2 + 0] = e0 * inv;
        out_probs[b * 2 + 1] = e1 * inv;
    }
}

__global__ void loss_kernel(const float* __restrict__ probs,
                            const int* __restrict__ label,
                            float* __restrict__ out_loss) {
    if (threadIdx.x == 0 && blockIdx.x == 0) {
        float acc = 0.f;
        for (int b = 0; b < BATCH; b++) {
            float p0 = probs[2 * b], p1 = probs[2 * b + 1];
            float m = fmaxf(p0, p1);
            float lse = m + logf(expf(p0 - m) + expf(p1 - m));
            float pl = (label[b] == 0) ? p0 : p1;
            acc += -(pl - lse);
        }
        out_loss[0] = acc * (1.0f / BATCH);
    }
}

// ---------------- Host driver ----------------
static void* sym_addr(const void* sym) {
    void* p = nullptr;
    cudaGetSymbolAddress(&p, sym);
    return p;
}

static void launch_split(const float* src, __nv_bfloat16* hi, __nv_bfloat16* lo, int n) {
    int n4 = n / 4;
    split_bf16_kernel<<<(n4 + 255) / 256, 256>>>(src, hi, lo, n4);
}

extern "C" void kernel_launch(void* const* d_in, const int* in_sizes, int n_in,
                              void* d_out, int out_size) {
    const int*   input_ids = (const int*)d_in[0];
    const int*   amask     = (const int*)d_in[1];
    const int*   label     = (const int*)d_in[2];
    const int*   rand_idx  = (const int*)d_in[3];
    const float* emb       = (const float*)d_in[4];
    const float* pos_emb   = (const float*)d_in[5];
    const float* ln_emb_g  = (const float*)d_in[6];
    const float* ln_emb_b  = (const float*)d_in[7];
    const float* Wqkv      = (const float*)d_in[8];
    const float* bqkv      = (const float*)d_in[9];
    const float* Wo        = (const float*)d_in[10];
    const float* bo        = (const float*)d_in[11];
    const float* ln1_g     = (const float*)d_in[12];
    const float* ln1_b     = (const float*)d_in[13];
    const float* Wff1      = (const float*)d_in[14];
    const float* bff1      = (const float*)d_in[15];
    const float* Wff2      = (const float*)d_in[16];
    const float* bff2      = (const float*)d_in[17];
    const float* ln2_g     = (const float*)d_in[18];
    const float* ln2_b     = (const float*)d_in[19];
    const float* Wp        = (const float*)d_in[20];
    const float* bp        = (const float*)d_in[21];
    const float* Wc        = (const float*)d_in[22];
    const float* bc        = (const float*)d_in[23];

    float* h_buf   = (float*)sym_addr(g_h);
    float* qkv_buf = (float*)sym_addr(g_qkv);
    float* o_buf   = (float*)sym_addr(g_o);
    float* tmp_buf = (float*)sym_addr(g_tmp);
    __nv_bfloat16* a_hi = (__nv_bfloat16*)sym_addr(g_a_hi);
    __nv_bfloat16* a_lo = (__nv_bfloat16*)sym_addr(g_a_lo);
    __nv_bfloat16* w_hi = (__nv_bfloat16*)sym_addr(g_w_hi);
    __nv_bfloat16* w_lo = (__nv_bfloat16*)sym_addr(g_w_lo);

    float* out = (float*)d_out;

    cudaFuncSetAttribute((const void*)gemm_mma_kernel<false>,
                         cudaFuncAttributeMaxDynamicSharedMemorySize, GEMM_SMEM_BYTES);
    cudaFuncSetAttribute((const void*)gemm_mma_kernel<true>,
                         cudaFuncAttributeMaxDynamicSharedMemorySize, GEMM_SMEM_BYTES);

    // weight splits (all layers at once; contiguous per weight tensor)
    launch_split(Wqkv, w_hi + OFF_WQKV, w_lo + OFF_WQKV, SZ_WQKV);
    launch_split(Wo,   w_hi + OFF_WO,   w_lo + OFF_WO,   SZ_WO);
    launch_split(Wff1, w_hi + OFF_WFF1, w_lo + OFF_WFF1, SZ_WFF1);
    launch_split(Wff2, w_hi + OFF_WFF2, w_lo + OFF_WFF2, SZ_WFF2);

    // embedding + LN
    embed_ln_kernel<<<NTOK, 256>>>(input_ids, emb, pos_emb, ln_emb_g, ln_emb_b, h_buf);

    for (int l = 0; l < NLAYER; l++) {
        const __nv_bfloat16* wqkv_hi = w_hi + OFF_WQKV + (size_t)l * DMODEL * 3 * DMODEL;
        const __nv_bfloat16* wqkv_lo = w_lo + OFF_WQKV + (size_t)l * DMODEL * 3 * DMODEL;
        const __nv_bfloat16* wo_hi   = w_hi + OFF_WO   + (size_t)l * DMODEL * DMODEL;
        const __nv_bfloat16* wo_lo   = w_lo + OFF_WO   + (size_t)l * DMODEL * DMODEL;
        const __nv_bfloat16* wff1_hi = w_hi + OFF_WFF1 + (size_t)l * DMODEL * FFDIM;
        const __nv_bfloat16* wff1_lo = w_lo + OFF_WFF1 + (size_t)l * DMODEL * FFDIM;
        const __nv_bfloat16* wff2_hi = w_hi + OFF_WFF2 + (size_t)l * FFDIM * DMODEL;
        const __nv_bfloat16* wff2_lo = w_lo + OFF_WFF2 + (size_t)l * FFDIM * DMODEL;
        const float* bqkv_l = bqkv + (size_t)l * 3 * DMODEL;
        const float* bo_l   = bo   + (size_t)l * DMODEL;
        const float* bff1_l = bff1 + (size_t)l * FFDIM;
        const float* bff2_l = bff2 + (size_t)l * DMODEL;

        // qkv = h @ Wqkv + bqkv
        launch_split(h_buf, a_hi, a_lo, NTOK * DMODEL);
        {
            dim3 grid(3 * DMODEL / BNT, NTOK / BMT);
            gemm_mma_kernel<false><<<grid, 256, GEMM_SMEM_BYTES>>>(
                a_hi, a_lo, wqkv_hi, wqkv_lo, bqkv_l, qkv_buf, NTOK, 3 * DMODEL, DMODEL);
        }
        // sparse attention
        {
            dim3 grid(NBLK, NHEAD, BATCH);
            attn_kernel<<<grid, 256>>>(qkv_buf, amask, rand_idx, o_buf);
        }
        // proj = o @ Wo + bo
        launch_split(o_buf, a_hi, a_lo, NTOK * DMODEL);
        {
            dim3 grid(DMODEL / BNT, NTOK / BMT);
            gemm_mma_kernel<false><<<grid, 256, GEMM_SMEM_BYTES>>>(
                a_hi, a_lo, wo_hi, wo_lo, bo_l, tmp_buf, NTOK, DMODEL, DMODEL);
        }
        ln_residual_kernel<<<NTOK, 256>>>(h_buf, tmp_buf, ln1_g + l * DMODEL, ln1_b + l * DMODEL);
        // ff1 = gelu(h @ Wff1 + bff1)
        launch_split(h_buf, a_hi, a_lo, NTOK * DMODEL);
        {
            dim3 grid(FFDIM / BNT, NTOK / BMT);
            gemm_mma_kernel<true><<<grid, 256, GEMM_SMEM_BYTES>>>(
                a_hi, a_lo, wff1_hi, wff1_lo, bff1_l, tmp_buf, NTOK, FFDIM, DMODEL);
        }
        // ff2 = ff1 @ Wff2 + bff2
        launch_split(tmp_buf, a_hi, a_lo, NTOK * FFDIM);
        {
            dim3 grid(DMODEL / BNT, NTOK / BMT);
            gemm_mma_kernel<false><<<grid, 256, GEMM_SMEM_BYTES>>>(
                a_hi, a_lo, wff2_hi, wff2_lo, bff2_l, o_buf, NTOK, DMODEL, FFDIM);
        }
        ln_residual_kernel<<<NTOK, 256>>>(h_buf, o_buf, ln2_g + l * DMODEL, ln2_b + l * DMODEL);
    }

    pooler_classify_kernel<<<BATCH, 256>>>(h_buf, Wp, bp, Wc, bc, out);
    loss_kernel<<<1, 32>>>(out, label, out + 8);
}

// round 3
// speedup vs baseline: 4.9799x; 1.9230x over previous
#include <cuda_runtime.h>
#include <cuda_bf16.h>
#include <math.h>
#include <stdint.h>

// ---------------- Model constants ----------------
#define BATCH 4
#define SEQ   4096
#define DMODEL 768
#define NHEAD 12
#define DHEAD 64
#define BLKS  64
#define NLAYER 2
#define NRAND 3
#define FFDIM 3072
#define NBLK  64
#define NSEL  8
#define NTOK  (BATCH*SEQ) // 16384

// weight bf16 buffer offsets (elements)
#define OFF_WQKV 0
#define SZ_WQKV  (NLAYER*DMODEL*3*DMODEL)
#define OFF_WO   (OFF_WQKV + SZ_WQKV)
#define SZ_WO    (NLAYER*DMODEL*DMODEL)
#define OFF_WFF1 (OFF_WO + SZ_WO)
#define SZ_WFF1  (NLAYER*DMODEL*FFDIM)
#define OFF_WFF2 (OFF_WFF1 + SZ_WFF1)
#define SZ_WFF2  (NLAYER*FFDIM*DMODEL)
#define WTOTAL   (OFF_WFF2 + SZ_WFF2)

// ---------------- Scratch (device globals) ----------------
__device__ __align__(16) float g_h[NTOK * DMODEL];
__device__ __align__(16) float g_t1[NTOK * DMODEL];
__device__ __align__(16) __nv_bfloat16 g_h_hi[NTOK * DMODEL];
__device__ __align__(16) __nv_bfloat16 g_h_lo[NTOK * DMODEL];
__device__ __align__(16) __nv_bfloat16 g_qkv_hi[NTOK * 3 * DMODEL];
__device__ __align__(16) __nv_bfloat16 g_qkv_lo[NTOK * 3 * DMODEL];
__device__ __align__(16) __nv_bfloat16 g_o_hi[NTOK * DMODEL];
__device__ __align__(16) __nv_bfloat16 g_o_lo[NTOK * DMODEL];
__device__ __align__(16) __nv_bfloat16 g_ff_hi[NTOK * FFDIM];
__device__ __align__(16) __nv_bfloat16 g_ff_lo[NTOK * FFDIM];
__device__ __align__(16) __nv_bfloat16 g_w_hi[WTOTAL];
__device__ __align__(16) __nv_bfloat16 g_w_lo[WTOTAL];

// ---------------- Helpers ----------------
__device__ __forceinline__ float gelu_tanh(float x) {
    float x3 = x * x * x;
    return 0.5f * x * (1.0f + tanhf(0.7978845608028654f * (x + 0.044715f * x3)));
}

__device__ __forceinline__ void split2(float v, __nv_bfloat16& hi, __nv_bfloat16& lo) {
    hi = __float2bfloat16(v);
    lo = __float2bfloat16(v - __bfloat162float(hi));
}

__device__ __forceinline__ void block_reduce2(float& s1, float& s2) {
    __shared__ float sh1[8], sh2[8];
    int lane = threadIdx.x & 31, w = threadIdx.x >> 5;
    #pragma unroll
    for (int o = 16; o > 0; o >>= 1) {
        s1 += __shfl_down_sync(0xffffffffu, s1, o);
        s2 += __shfl_down_sync(0xffffffffu, s2, o);
    }
    if (lane == 0) { sh1[w] = s1; sh2[w] = s2; }
    __syncthreads();
    if (w == 0) {
        s1 = (lane < 8) ? sh1[lane] : 0.f;
        s2 = (lane < 8) ? sh2[lane] : 0.f;
        #pragma unroll
        for (int o = 4; o > 0; o >>= 1) {
            s1 += __shfl_down_sync(0xffffffffu, s1, o);
            s2 += __shfl_down_sync(0xffffffffu, s2, o);
        }
        if (lane == 0) { sh1[0] = s1; sh2[0] = s2; }
    }
    __syncthreads();
    s1 = sh1[0]; s2 = sh2[0];
}

// ---------------- fp32 -> bf16 hi/lo split (weights only) ----------------
__global__ void split_bf16_kernel(const float* __restrict__ x,
                                  __nv_bfloat16* __restrict__ hi,
                                  __nv_bfloat16* __restrict__ lo, int n4) {
    int i = blockIdx.x * blockDim.x + threadIdx.x;
    if (i >= n4) return;
    float4 v = reinterpret_cast<const float4*>(x)[i];
    __nv_bfloat16 h0, h1, h2, h3, l0, l1, l2, l3;
    split2(v.x, h0, l0); split2(v.y, h1, l1);
    split2(v.z, h2, l2); split2(v.w, h3, l3);
    __nv_bfloat162 hp0{h0, h1}, hp1{h2, h3}, lp0{l0, l1}, lp1{l2, l3};
    reinterpret_cast<__nv_bfloat162*>(hi)[2 * i]     = hp0;
    reinterpret_cast<__nv_bfloat162*>(hi)[2 * i + 1] = hp1;
    reinterpret_cast<__nv_bfloat162*>(lo)[2 * i]     = lp0;
    reinterpret_cast<__nv_bfloat162*>(lo)[2 * i + 1] = lp1;
}

// ---------------- Embedding + LayerNorm (writes fp32 + hi/lo planes) ----------------
__global__ void embed_ln_kernel(const int* __restrict__ ids,
                                const float* __restrict__ emb,
                                const float* __restrict__ pos,
                                const float* __restrict__ g,
                                const float* __restrict__ b,
                                float* __restrict__ out,
                                __nv_bfloat16* __restrict__ ohi,
                                __nv_bfloat16* __restrict__ olo) {
    int tok = blockIdx.x;
    int s = tok % SEQ;
    int id = ids[tok];
    const float* erow = emb + (size_t)id * DMODEL;
    const float* prow = pos + (size_t)s * DMODEL;
    float v[3];
    float sum = 0.f, sumsq = 0.f;
    #pragma unroll
    for (int i = 0; i < 3; i++) {
        int d = threadIdx.x + i * 256;
        v[i] = erow[d] + prow[d];
        sum += v[i]; sumsq += v[i] * v[i];
    }
    block_reduce2(sum, sumsq);
    float mean = sum * (1.0f / DMODEL);
    float var = sumsq * (1.0f / DMODEL) - mean * mean;
    float rstd = rsqrtf(var + 1e-12f);
    size_t rb = (size_t)tok * DMODEL;
    #pragma unroll
    for (int i = 0; i < 3; i++) {
        int d = threadIdx.x + i * 256;
        float o = (v[i] - mean) * rstd * g[d] + b[d];
        out[rb + d] = o;
        __nv_bfloat16 hh, ll; split2(o, hh, ll);
        ohi[rb + d] = hh; olo[rb + d] = ll;
    }
}

__global__ void ln_residual_kernel(float* __restrict__ h,
                                   const float* __restrict__ x,
                                   const float* __restrict__ g,
                                   const float* __restrict__ b,
                                   __nv_bfloat16* __restrict__ ohi,
                                   __nv_bfloat16* __restrict__ olo) {
    int tok = blockIdx.x;
    size_t rb = (size_t)tok * DMODEL;
    float* hrow = h + rb;
    const float* xrow = x + rb;
    float v[3];
    float sum = 0.f, sumsq = 0.f;
    #pragma unroll
    for (int i = 0; i < 3; i++) {
        int d = threadIdx.x + i * 256;
        v[i] = hrow[d] + xrow[d];
        sum += v[i]; sumsq += v[i] * v[i];
    }
    block_reduce2(sum, sumsq);
    float mean = sum * (1.0f / DMODEL);
    float var = sumsq * (1.0f / DMODEL) - mean * mean;
    float rstd = rsqrtf(var + 1e-12f);
    #pragma unroll
    for (int i = 0; i < 3; i++) {
        int d = threadIdx.x + i * 256;
        float o = (v[i] - mean) * rstd * g[d] + b[d];
        hrow[d] = o;
        __nv_bfloat16 hh, ll; split2(o, hh, ll);
        ohi[rb + d] = hh; olo[rb + d] = ll;
    }
}

// ---------------- MMA primitives ----------------
__device__ __forceinline__ uint32_t smem_u32(const void* p) {
    return (uint32_t)__cvta_generic_to_shared(p);
}
__device__ __forceinline__ void ldmatrix_x4(uint32_t* r, uint32_t addr) {
    asm volatile("ldmatrix.sync.aligned.m8n8.x4.shared.b16 {%0,%1,%2,%3}, [%4];"
                 : "=r"(r[0]), "=r"(r[1]), "=r"(r[2]), "=r"(r[3]) : "r"(addr));
}
__device__ __forceinline__ void ldmatrix_x4_t(uint32_t* r, uint32_t addr) {
    asm volatile("ldmatrix.sync.aligned.m8n8.x4.trans.shared.b16 {%0,%1,%2,%3}, [%4];"
                 : "=r"(r[0]), "=r"(r[1]), "=r"(r[2]), "=r"(r[3]) : "r"(addr));
}
__device__ __forceinline__ void mma_bf16(float* d, const uint32_t* a, const uint32_t* b) {
    asm volatile("mma.sync.aligned.m16n8k16.row.col.f32.bf16.bf16.f32 "
                 "{%0,%1,%2,%3}, {%4,%5,%6,%7}, {%8,%9}, {%0,%1,%2,%3};"
                 : "+f"(d[0]), "+f"(d[1]), "+f"(d[2]), "+f"(d[3])
                 : "r"(a[0]), "r"(a[1]), "r"(a[2]), "r"(a[3]), "r"(b[0]), "r"(b[1]));
}
__device__ __forceinline__ void cp_async16(void* dst, const void* src) {
    asm volatile("cp.async.cg.shared.global [%0], [%1], 16;"
                 :: "r"(smem_u32(dst)), "l"(src));
}

// ---------------- Tensor-core GEMM (bf16 hi/lo split, fp32 accum) ----------------
#define BMT 128
#define BNT 128
#define BKT 32
#define SA  40
#define SB  136
#define ASTAGE (2 * BMT * SA)
#define BSTAGE (2 * BKT * SB)
#define STAGE_E (ASTAGE + BSTAGE)
#define GEMM_SMEM_BYTES (2 * STAGE_E * 2)

// OUT_SPLIT: write Chi/Clo bf16 planes; else write fp32 C.
template <bool GELU, bool OUT_SPLIT>
__global__ __launch_bounds__(256, 1) void gemm_mma_kernel(
    const __nv_bfloat16* __restrict__ Ahi, const __nv_bfloat16* __restrict__ Alo,
    const __nv_bfloat16* __restrict__ Bhi, const __nv_bfloat16* __restrict__ Blo,
    const float* __restrict__ bias, float* __restrict__ C,
    __nv_bfloat16* __restrict__ Chi, __nv_bfloat16* __restrict__ Clo,
    int M, int N, int K)
{
    extern __shared__ __nv_bfloat16 smx[];
    const int tid = threadIdx.x;
    const int wid = tid >> 5;
    const int lane = tid & 31;
    const int m0 = blockIdx.y * BMT;
    const int n0 = blockIdx.x * BNT;
    const int wm0 = (wid & 3) * 32;
    const int wn0 = (wid >> 2) * 64;

    float acc[2][8][4];
    #pragma unroll
    for (int i = 0; i < 2; i++)
        #pragma unroll
        for (int j = 0; j < 8; j++)
            #pragma unroll
            for (int c = 0; c < 4; c++) acc[i][j][c] = 0.f;

    const int nk = K / BKT;

    auto load_stage = [&](int s, int k0) {
        __nv_bfloat16* base = smx + s * STAGE_E;
        #pragma unroll
        for (int t = 0; t < 4; t++) {
            int idx = tid + t * 256;
            int plane = idx >> 9;
            int rem = idx & 511;
            int r = rem >> 2;
            int c = (rem & 3) << 3;
            const __nv_bfloat16* src =
                (plane ? Alo : Ahi) + (size_t)(m0 + r) * K + k0 + c;
            cp_async16(base + plane * (BMT * SA) + r * SA + c, src);
        }
        __nv_bfloat16* bb = base + ASTAGE;
        #pragma unroll
        for (int t = 0; t < 4; t++) {
            int idx = tid + t * 256;
            int plane = idx >> 9;
            int rem = idx & 511;
            int r = rem >> 4;
            int c = (rem & 15) << 3;
            const __nv_bfloat16* src =
                (plane ? Blo : Bhi) + (size_t)(k0 + r) * N + n0 + c;
            cp_async16(bb + plane * (BKT * SB) + r * SB + c, src);
        }
    };

    load_stage(0, 0);
    asm volatile("cp.async.commit_group;");

    for (int kt = 0; kt < nk; kt++) {
        if (kt + 1 < nk) load_stage((kt + 1) & 1, (kt + 1) * BKT);
        asm volatile("cp.async.commit_group;");
        asm volatile("cp.async.wait_group 1;");
        __syncthreads();

        const int s = kt & 1;
        const __nv_bfloat16* As0 = smx + s * STAGE_E;
        const __nv_bfloat16* As1 = As0 + BMT * SA;
        const __nv_bfloat16* Bs0 = smx + s * STAGE_E + ASTAGE;
        const __nv_bfloat16* Bs1 = Bs0 + BKT * SB;

        #pragma unroll
        for (int kk = 0; kk < BKT; kk += 16) {
            uint32_t af[2][2][4];
            #pragma unroll
            for (int mi = 0; mi < 2; mi++) {
                int row = wm0 + mi * 16 + (lane & 15);
                int col = kk + ((lane >> 4) << 3);
                ldmatrix_x4(af[0][mi], smem_u32(As0 + row * SA + col));
                ldmatrix_x4(af[1][mi], smem_u32(As1 + row * SA + col));
            }
            uint32_t bfr[2][4][4];
            #pragma unroll
            for (int ni = 0; ni < 4; ni++) {
                int rr = kk + (lane & 15);
                int cc = wn0 + ni * 16 + ((lane >> 4) << 3);
                ldmatrix_x4_t(bfr[0][ni], smem_u32(Bs0 + rr * SB + cc));
                ldmatrix_x4_t(bfr[1][ni], smem_u32(Bs1 + rr * SB + cc));
            }
            #pragma unroll
            for (int mi = 0; mi < 2; mi++)
                #pragma unroll
                for (int ni = 0; ni < 4; ni++)
                    #pragma unroll
                    for (int hf = 0; hf < 2; hf++) {
                        int nj = ni * 2 + hf;
                        const uint32_t* bh = &bfr[0][ni][hf * 2];
                        const uint32_t* bl = &bfr[1][ni][hf * 2];
                        mma_bf16(acc[mi][nj], af[0][mi], bh);
                        mma_bf16(acc[mi][nj], af[0][mi], bl);
                        mma_bf16(acc[mi][nj], af[1][mi], bh);
                    }
        }
        __syncthreads();
    }

    #pragma unroll
    for (int mi = 0; mi < 2; mi++) {
        int gr = m0 + wm0 + mi * 16 + (lane >> 2);
        #pragma unroll
        for (int nj = 0; nj < 8; nj++) {
            int gc = n0 + wn0 + nj * 8 + (lane & 3) * 2;
            float b0 = bias[gc], b1 = bias[gc + 1];
            float v0 = acc[mi][nj][0] + b0;
            float v1 = acc[mi][nj][1] + b1;
            float v2 = acc[mi][nj][2] + b0;
            float v3 = acc[mi][nj][3] + b1;
            if (GELU) {
                v0 = gelu_tanh(v0); v1 = gelu_tanh(v1);
                v2 = gelu_tanh(v2); v3 = gelu_tanh(v3);
            }
            if (OUT_SPLIT) {
                __nv_bfloat16 h0, h1, h2, h3, l0, l1, l2, l3;
                split2(v0, h0, l0); split2(v1, h1, l1);
                split2(v2, h2, l2); split2(v3, h3, l3);
                __nv_bfloat162 ph0{h0, h1}, ph1{h2, h3}, pl0{l0, l1}, pl1{l2, l3};
                *reinterpret_cast<__nv_bfloat162*>(&Chi[(size_t)gr * N + gc]) = ph0;
                *reinterpret_cast<__nv_bfloat162*>(&Chi[(size_t)(gr + 8) * N + gc]) = ph1;
                *reinterpret_cast<__nv_bfloat162*>(&Clo[(size_t)gr * N + gc]) = pl0;
                *reinterpret_cast<__nv_bfloat162*>(&Clo[(size_t)(gr + 8) * N + gc]) = pl1;
            } else {
                float2 p0{v0, v1}, p1{v2, v3};
                *reinterpret_cast<float2*>(&C[(size_t)gr * N + gc]) = p0;
                *reinterpret_cast<float2*>(&C[(size_t)(gr + 8) * N + gc]) = p1;
            }
        }
    }
}

// ---------------- MMA block-sparse flash attention ----------------
#define ATS 72                 // smem row stride (bf16)
#define AT_PL (64 * ATS)       // one 64x64 plane
#define AT_KV_STAGE (4 * AT_PL)
#define ATTN_SMEM_BYTES ((2*AT_PL + 2*AT_KV_STAGE + 2*AT_PL) * 2 + 384 * 4)

__device__ __forceinline__ int sel_block(int i, int nb, const int* __restrict__ rand_idx) {
    switch (i) {
        case 0: return 0;
        case 1: return (nb + NBLK - 1) % NBLK;
        case 2: return nb;
        case 3: return (nb + 1) % NBLK;
        case 4: return NBLK - 1;
        default: return rand_idx[nb * NRAND + (i - 5)];
    }
}

__global__ __launch_bounds__(256, 1) void attn_mma_kernel(
    const __nv_bfloat16* __restrict__ qkv_hi,
    const __nv_bfloat16* __restrict__ qkv_lo,
    const int* __restrict__ amask, const int* __restrict__ rand_idx,
    __nv_bfloat16* __restrict__ o_hi, __nv_bfloat16* __restrict__ o_lo)
{
    extern __shared__ char smraw[];
    __nv_bfloat16* q_h = reinterpret_cast<__nv_bfloat16*>(smraw);
    __nv_bfloat16* q_l = q_h + AT_PL;
    __nv_bfloat16* kvb = q_l + AT_PL;                 // 2 stages follow
    __nv_bfloat16* p_h = kvb + 2 * AT_KV_STAGE;
    __nv_bfloat16* p_l = p_h + AT_PL;
    float* bias_s = reinterpret_cast<float*>(p_l + AT_PL);  // [2][64]
    float* redm   = bias_s + 128;                           // [2][64]
    float* reds   = redm + 128;                             // [2][64]

    const int nb = blockIdx.x;
    const int h  = blockIdx.y;
    const int b  = blockIdx.z;
    const int tid = threadIdx.x;
    const int wid = tid >> 5;
    const int lane = tid & 31;
    const int wm = (wid & 3) * 16;         // m stripe (query rows)
    const int wn = (wid >> 2) * 32;        // n stripe (keys / out dims)
    const int nw = wid >> 2;               // n-warp id

    const size_t q_base = (size_t)b * SEQ + nb * BLKS;

    auto load_chunk = [&](int i) {
        int sb = sel_block(i, nb, rand_idx);
        size_t bt = (size_t)b * SEQ + sb * BLKS;
        __nv_bfloat16* st = kvb + (i & 1) * AT_KV_STAGE;
        #pragma unroll
        for (int t = 0; t < 8; t++) {
            int idx = tid + t * 256;        // 2048 16B chunks
            int arr = idx >> 9;             // 0:k_hi 1:k_lo 2:v_hi 3:v_lo
            int rem = idx & 511;
            int row = rem >> 3;
            int c = (rem & 7) * 8;
            const __nv_bfloat16* srcb = (arr & 1) ? qkv_lo : qkv_hi;
            int off = (arr >> 1) ? 2 * DMODEL : DMODEL;
            const __nv_bfloat16* src = srcb + (bt + row) * (3 * DMODEL) + off + h * DHEAD + c;
            cp_async16(st + arr * AT_PL + row * ATS + c, src);
        }
        if (tid < 64)
            bias_s[(i & 1) * 64 + tid] =
                (amask[b * SEQ + sb * BLKS + tid] > 0) ? 0.f : -1e9f;
    };

    // ---- prologue: Q + chunk0 (group 0), chunk1 (group 1) ----
    #pragma unroll
    for (int t = 0; t < 4; t++) {
        int idx = tid + t * 256;           // 1024 chunks
        int plane = idx >> 9;
        int rem = idx & 511;
        int row = rem >> 3;
        int c = (rem & 7) * 8;
        const __nv_bfloat16* src =
            ((plane ? qkv_lo : qkv_hi)) + (q_base + row) * (3 * DMODEL) + h * DHEAD + c;
        cp_async16((plane ? q_l : q_h) + row * ATS + c, src);
    }
    load_chunk(0);
    asm volatile("cp.async.commit_group;");
    load_chunk(1);
    asm volatile("cp.async.commit_group;");

    asm volatile("cp.async.wait_group 1;");
    __syncthreads();
    // scale Q by 1/8 (exact in bf16; preserves hi/lo decomposition)
    {
        const __nv_bfloat162 sc2 = __floats2bfloat162_rn(0.125f, 0.125f);
        #pragma unroll
        for (int t = 0; t < 16; t++) {
            int idx = tid + t * 256;       // 4096 bf16x2
            int plane = idx >> 11;
            int rem = idx & 2047;
            int row = rem >> 5;
            int cp = rem & 31;
            __nv_bfloat162* p = reinterpret_cast<__nv_bfloat162*>(
                (plane ? q_l : q_h) + row * ATS + cp * 2);
            *p = __hmul2(*p, sc2);
        }
    }
    __syncthreads();

    float s_m[2] = {-INFINITY, -INFINITY};
    float s_l[2] = {0.f, 0.f};
    float oacc[4][4];
    #pragma unroll
    for (int j = 0; j < 4; j++)
        #pragma unroll
        for (int c = 0; c < 4; c++) oacc[j][c] = 0.f;

    const int R0 = wm + (lane >> 2);

    for (int i = 0; i < NSEL; i++) {
        if (i > 0) {
            asm volatile("cp.async.wait_group 1;");
            __syncthreads();
        }
        const __nv_bfloat16* kh = kvb + (i & 1) * AT_KV_STAGE;
        const __nv_bfloat16* kl = kh + AT_PL;
        const __nv_bfloat16* vh = kh + 2 * AT_PL;
        const __nv_bfloat16* vl = kh + 3 * AT_PL;

        // ---- S = Q*K^T (3-product hi/lo) ----
        float scf[4][4];
        #pragma unroll
        for (int j = 0; j < 4; j++)
            #pragma unroll
            for (int c = 0; c < 4; c++) scf[j][c] = 0.f;

        #pragma unroll
        for (int kk = 0; kk < 64; kk += 16) {
            uint32_t aq_h[4], aq_l[4];
            {
                int row = wm + (lane & 15);
                int col = kk + ((lane >> 4) << 3);
                ldmatrix_x4(aq_h, smem_u32(q_h + row * ATS + col));
                ldmatrix_x4(aq_l, smem_u32(q_l + row * ATS + col));
            }
            uint32_t bk_h[2][4], bk_l[2][4];
            {
                int brow = (lane & 7) + ((lane >> 4) << 3);
                int bcol = kk + (lane & 8);
                #pragma unroll
                for (int np = 0; np < 2; np++) {
                    int r = wn + np * 16 + brow;
                    ldmatrix_x4(bk_h[np], smem_u32(kh + r * ATS + bcol));
                    ldmatrix_x4(bk_l[np], smem_u32(kl + r * ATS + bcol));
                }
            }
            #pragma unroll
            for (int j = 0; j < 4; j++) {
                const uint32_t* bh = &bk_h[j >> 1][(j & 1) * 2];
                const uint32_t* bl = &bk_l[j >> 1][(j & 1) * 2];
                mma_bf16(scf[j], aq_h, bh);
                mma_bf16(scf[j], aq_h, bl);
                mma_bf16(scf[j], aq_l, bh);
            }
        }

        // ---- bias + online softmax ----
        float lm0 = -INFINITY, lm1 = -INFINITY;
        #pragma unroll
        for (int j = 0; j < 4; j++) {
            int cb = wn + j * 8 + (lane & 3) * 2;
            float b0 = bias_s[(i & 1) * 64 + cb];
            float b1 = bias_s[(i & 1) * 64 + cb + 1];
            scf[j][0] += b0; scf[j][1] += b1;
            scf[j][2] += b0; scf[j][3] += b1;
            lm0 = fmaxf(lm0, fmaxf(scf[j][0], scf[j][1]));
            lm1 = fmaxf(lm1, fmaxf(scf[j][2], scf[j][3]));
        }
        lm0 = fmaxf(lm0, __shfl_xor_sync(0xffffffffu, lm0, 1));
        lm0 = fmaxf(lm0, __shfl_xor_sync(0xffffffffu, lm0, 2));
        lm1 = fmaxf(lm1, __shfl_xor_sync(0xffffffffu, lm1, 1));
        lm1 = fmaxf(lm1, __shfl_xor_sync(0xffffffffu, lm1, 2));
        if ((lane & 3) == 0) {
            redm[nw * 64 + R0] = lm0;
            redm[nw * 64 + R0 + 8] = lm1;
        }
        __syncthreads();
        float cm0 = fmaxf(redm[R0], redm[64 + R0]);
        float cm1 = fmaxf(redm[R0 + 8], redm[64 + R0 + 8]);
        float mn0 = fmaxf(s_m[0], cm0);
        float mn1 = fmaxf(s_m[1], cm1);
        float corr0 = __expf(s_m[0] - mn0);
        float corr1 = __expf(s_m[1] - mn1);
        s_m[0] = mn0; s_m[1] = mn1;

        float ls0 = 0.f, ls1 = 0.f;
        #pragma unroll
        for (int j = 0; j < 4; j++) {
            int cb = wn + j * 8 + (lane & 3) * 2;
            float p0 = __expf(scf[j][0] - mn0);
            float p1 = __expf(scf[j][1] - mn1 + (mn1 - mn1)); // placeholder fix below
            p1 = __expf(scf[j][1] - mn0);
            float p2 = __expf(scf[j][2] - mn1);
            float p3 = __expf(scf[j][3] - mn1);
            ls0 += p0 + p1;
            ls1 += p2 + p3;
            __nv_bfloat16 h0, h1, h2, h3, l0, l1, l2, l3;
            split2(p0, h0, l0); split2(p1, h1, l1);
            split2(p2, h2, l2); split2(p3, h3, l3);
            __nv_bfloat162 ph0{h0, h1}, ph1{h2, h3}, pl0{l0, l1}, pl1{l2, l3};
            *reinterpret_cast<__nv_bfloat162*>(p_h + R0 * ATS + cb) = ph0;
            *reinterpret_cast<__nv_bfloat162*>(p_h + (R0 + 8) * ATS + cb) = ph1;
            *reinterpret_cast<__nv_bfloat162*>(p_l + R0 * ATS + cb) = pl0;
            *reinterpret_cast<__nv_bfloat162*>(p_l + (R0 + 8) * ATS + cb) = pl1;
            // rescale running O
            oacc[j][0] *= corr0; oacc[j][1] *= corr0;
            oacc[j][2] *= corr1; oacc[j][3] *= corr1;
        }
        ls0 += __shfl_xor_sync(0xffffffffu, ls0, 1);
        ls0 += __shfl_xor_sync(0xffffffffu, ls0, 2);
        ls1 += __shfl_xor_sync(0xffffffffu, ls1, 1);
        ls1 += __shfl_xor_sync(0xffffffffu, ls1, 2);
        if ((lane & 3) == 0) {
            reds[nw * 64 + R0] = ls0;
            reds[nw * 64 + R0 + 8] = ls1;
        }
        __syncthreads();
        s_l[0] = s_l[0] * corr0 + reds[R0] + reds[64 + R0];
        s_l[1] = s_l[1] * corr1 + reds[R0 + 8] + reds[64 + R0 + 8];

        // ---- O += P*V (3-product hi/lo) ----
        #pragma unroll
        for (int kk = 0; kk < 64; kk += 16) {
            uint32_t ap_h[4], ap_l[4];
            {
                int row = wm + (lane & 15);
                int col = kk + ((lane >> 4) << 3);
                ldmatrix_x4(ap_h, smem_u32(p_h + row * ATS + col));
                ldmatrix_x4(ap_l, smem_u32(p_l + row * ATS + col));
            }
            uint32_t bv_h[2][4], bv_l[2][4];
            {
                int rr = kk + (lane & 15);
                #pragma unroll
                for (int np = 0; np < 2; np++) {
                    int cc = wn + np * 16 + ((lane >> 4) << 3);
                    ldmatrix_x4_t(bv_h[np], smem_u32(vh + rr * ATS + cc));
                    ldmatrix_x4_t(bv_l[np], smem_u32(vl + rr * ATS + cc));
                }
            }
            #pragma unroll
            for (int j = 0; j < 4; j++) {
                const uint32_t* bh = &bv_h[j >> 1][(j & 1) * 2];
                const uint32_t* bl = &bv_l[j >> 1][(j & 1) * 2];
                mma_bf16(oacc[j], ap_h, bh);
                mma_bf16(oacc[j], ap_h, bl);
                mma_bf16(oacc[j], ap_l, bh);
            }
        }
        __syncthreads();   // stage & P consumed; safe to overwrite
        if (i + 2 < NSEL) load_chunk(i + 2);
        asm volatile("cp.async.commit_group;");
    }

    // ---- epilogue ----
    float inv0 = 1.0f / s_l[0];
    float inv1 = 1.0f / s_l[1];
    size_t tok0 = q_base + R0;
    #pragma unroll
    for (int j = 0; j < 4; j++) {
        int gc = h * DHEAD + wn + j * 8 + (lane & 3) * 2;
        float v0 = oacc[j][0] * inv0;
        float v1 = oacc[j][1] * inv0;
        float v2 = oacc[j][2] * inv1;
        float v3 = oacc[j][3] * inv1;
        __nv_bfloat16 h0, h1, h2, h3, l0, l1, l2, l3;
        split2(v0, h0, l0); split2(v1, h1, l1);
        split2(v2, h2, l2); split2(v3, h3, l3);
        __nv_bfloat162 ph0{h0, h1}, ph1{h2, h3}, pl0{l0, l1}, pl1{l2, l3};
        *reinterpret_cast<__nv_bfloat162*>(&o_hi[tok0 * DMODEL + gc]) = ph0;
        *reinterpret_cast<__nv_bfloat162*>(&o_hi[(tok0 + 8) * DMODEL + gc]) = ph1;
        *reinterpret_cast<__nv_bfloat162*>(&o_lo[tok0 * DMODEL + gc]) = pl0;
        *reinterpret_cast<__nv_bfloat162*>(&o_lo[(tok0 + 8) * DMODEL + gc]) = pl1;
    }
}

// ---------------- Pooler + classifier ----------------
__global__ void pooler_classify_kernel(const float* __restrict__ h,
                                       const float* __restrict__ Wp,
                                       const float* __restrict__ bp,
                                       const float* __restrict__ Wc,
                                       const float* __restrict__ bc,
                                       float* __restrict__ out_probs) {
    int b = blockIdx.x;
    __shared__ float pooled[DMODEL];
    const float* hrow = h + (size_t)b * SEQ * DMODEL;
    for (int d = threadIdx.x; d < DMODEL; d += blockDim.x) {
        float s = bp[d];
        for (int k = 0; k < DMODEL; k++) s = fmaf(hrow[k], Wp[(size_t)k * DMODEL + d], s);
        pooled[d] = tanhf(s);
    }
    __syncthreads();
    if (threadIdx.x == 0) {
        float l0 = bc[0], l1 = bc[1];
        for (int k = 0; k < DMODEL; k++) {
            l0 = fmaf(pooled[k], Wc[2 * k + 0], l0);
            l1 = fmaf(pooled[k], Wc[2 * k + 1], l1);
        }
        float m = fmaxf(l0, l1);
        float e0 = expf(l0 - m), e1 = expf(l1 - m);
        float inv = 1.0f / (e0 + e1);
        out_probs[b * 2 + 0] = e0 * inv;
        out_probs[b * 2 + 1] = e1 * inv;
    }
}

__global__ void loss_kernel(const float* __restrict__ probs,
                            const int* __restrict__ label,
                            float* __restrict__ out_loss) {
    if (threadIdx.x == 0 && blockIdx.x == 0) {
        float acc = 0.f;
        for (int b = 0; b < BATCH; b++) {
            float p0 = probs[2 * b], p1 = probs[2 * b + 1];
            float m = fmaxf(p0, p1);
            float lse = m + logf(expf(p0 - m) + expf(p1 - m));
            float pl = (label[b] == 0) ? p0 : p1;
            acc += -(pl - lse);
        }
        out_loss[0] = acc * (1.0f / BATCH);
    }
}

// ---------------- Host driver ----------------
static void* sym_addr(const void* sym) {
    void* p = nullptr;
    cudaGetSymbolAddress(&p, sym);
    return p;
}

static void launch_split(const float* src, __nv_bfloat16* hi, __nv_bfloat16* lo, int n) {
    int n4 = n / 4;
    split_bf16_kernel<<<(n4 + 255) / 256, 256>>>(src, hi, lo, n4);
}

extern "C" void kernel_launch(void* const* d_in, const int* in_sizes, int n_in,
                              void* d_out, int out_size) {
    const int*   input_ids = (const int*)d_in[0];
    const int*   amask     = (const int*)d_in[1];
    const int*   label     = (const int*)d_in[2];
    const int*   rand_idx  = (const int*)d_in[3];
    const float* emb       = (const float*)d_in[4];
    const float* pos_emb   = (const float*)d_in[5];
    const float* ln_emb_g  = (const float*)d_in[6];
    const float* ln_emb_b  = (const float*)d_in[7];
    const float* Wqkv      = (const float*)d_in[8];
    const float* bqkv      = (const float*)d_in[9];
    const float* Wo        = (const float*)d_in[10];
    const float* bo        = (const float*)d_in[11];
    const float* ln1_g     = (const float*)d_in[12];
    const float* ln1_b     = (const float*)d_in[13];
    const float* Wff1      = (const float*)d_in[14];
    const float* bff1      = (const float*)d_in[15];
    const float* Wff2      = (const float*)d_in[16];
    const float* bff2      = (const float*)d_in[17];
    const float* ln2_g     = (const float*)d_in[18];
    const float* ln2_b     = (const float*)d_in[19];
    const float* Wp        = (const float*)d_in[20];
    const float* bp        = (const float*)d_in[21];
    const float* Wc        = (const float*)d_in[22];
    const float* bc        = (const float*)d_in[23];

    float* h_buf  = (float*)sym_addr(g_h);
    float* t1_buf = (float*)sym_addr(g_t1);
    __nv_bfloat16* h_hi   = (__nv_bfloat16*)sym_addr(g_h_hi);
    __nv_bfloat16* h_lo   = (__nv_bfloat16*)sym_addr(g_h_lo);
    __nv_bfloat16* qkv_hi = (__nv_bfloat16*)sym_addr(g_qkv_hi);
    __nv_bfloat16* qkv_lo = (__nv_bfloat16*)sym_addr(g_qkv_lo);
    __nv_bfloat16* o_hi   = (__nv_bfloat16*)sym_addr(g_o_hi);
    __nv_bfloat16* o_lo   = (__nv_bfloat16*)sym_addr(g_o_lo);
    __nv_bfloat16* ff_hi  = (__nv_bfloat16*)sym_addr(g_ff_hi);
    __nv_bfloat16* ff_lo  = (__nv_bfloat16*)sym_addr(g_ff_lo);
    __nv_bfloat16* w_hi   = (__nv_bfloat16*)sym_addr(g_w_hi);
    __nv_bfloat16* w_lo   = (__nv_bfloat16*)sym_addr(g_w_lo);

    float* out = (float*)d_out;

    cudaFuncSetAttribute((const void*)gemm_mma_kernel<false, false>,
                         cudaFuncAttributeMaxDynamicSharedMemorySize, GEMM_SMEM_BYTES);
    cudaFuncSetAttribute((const void*)gemm_mma_kernel<false, true>,
                         cudaFuncAttributeMaxDynamicSharedMemorySize, GEMM_SMEM_BYTES);
    cudaFuncSetAttribute((const void*)gemm_mma_kernel<true, true>,
                         cudaFuncAttributeMaxDynamicSharedMemorySize, GEMM_SMEM_BYTES);
    cudaFuncSetAttribute((const void*)attn_mma_kernel,
                         cudaFuncAttributeMaxDynamicSharedMemorySize, ATTN_SMEM_BYTES);

    // weight splits
    launch_split(Wqkv, w_hi + OFF_WQKV, w_lo + OFF_WQKV, SZ_WQKV);
    launch_split(Wo,   w_hi + OFF_WO,   w_lo + OFF_WO,   SZ_WO);
    launch_split(Wff1, w_hi + OFF_WFF1, w_lo + OFF_WFF1, SZ_WFF1);
    launch_split(Wff2, w_hi + OFF_WFF2, w_lo + OFF_WFF2, SZ_WFF2);

    embed_ln_kernel<<<NTOK, 256>>>(input_ids, emb, pos_emb, ln_emb_g, ln_emb_b,
                                   h_buf, h_hi, h_lo);

    for (int l = 0; l < NLAYER; l++) {
        const __nv_bfloat16* wqkv_hi = w_hi + OFF_WQKV + (size_t)l * DMODEL * 3 * DMODEL;
        const __nv_bfloat16* wqkv_lo = w_lo + OFF_WQKV + (size_t)l * DMODEL * 3 * DMODEL;
        const __nv_bfloat16* wo_hi   = w_hi + OFF_WO   + (size_t)l * DMODEL * DMODEL;
        const __nv_bfloat16* wo_lo   = w_lo + OFF_WO   + (size_t)l * DMODEL * DMODEL;
        const __nv_bfloat16* wff1_hi = w_hi + OFF_WFF1 + (size_t)l * DMODEL * FFDIM;
        const __nv_bfloat16* wff1_lo = w_lo + OFF_WFF1 + (size_t)l * DMODEL * FFDIM;
        const __nv_bfloat16* wff2_hi = w_hi + OFF_WFF2 + (size_t)l * FFDIM * DMODEL;
        const __nv_bfloat16* wff2_lo = w_lo + OFF_WFF2 + (size_t)l * FFDIM * DMODEL;
        const float* bqkv_l = bqkv + (size_t)l * 3 * DMODEL;
        const float* bo_l   = bo   + (size_t)l * DMODEL;
        const float* bff1_l = bff1 + (size_t)l * FFDIM;
        const float* bff2_l = bff2 + (size_t)l * DMODEL;

        // qkv (bf16 hi/lo out)
        {
            dim3 grid(3 * DMODEL / BNT, NTOK / BMT);
            gemm_mma_kernel<false, true><<<grid, 256, GEMM_SMEM_BYTES>>>(
                h_hi, h_lo, wqkv_hi, wqkv_lo, bqkv_l,
                nullptr, qkv_hi, qkv_lo, NTOK, 3 * DMODEL, DMODEL);
        }
        // attention (bf16 hi/lo out)
        {
            dim3 grid(NBLK, NHEAD, BATCH);
            attn_mma_kernel<<<grid, 256, ATTN_SMEM_BYTES>>>(
                qkv_hi, qkv_lo, amask, rand_idx, o_hi, o_lo);
        }
        // o-proj (fp32 out)
        {
            dim3 grid(DMODEL / BNT, NTOK / BMT);
            gemm_mma_kernel<false, false><<<grid, 256, GEMM_SMEM_BYTES>>>(
                o_hi, o_lo, wo_hi, wo_lo, bo_l,
                t1_buf, nullptr, nullptr, NTOK, DMODEL, DMODEL);
        }
        ln_residual_kernel<<<NTOK, 256>>>(h_buf, t1_buf,
                                          ln1_g + l * DMODEL, ln1_b + l * DMODEL,
                                          h_hi, h_lo);
        // ff1 gelu (bf16 hi/lo out)
        {
            dim3 grid(FFDIM / BNT, NTOK / BMT);
            gemm_mma_kernel<true, true><<<grid, 256, GEMM_SMEM_BYTES>>>(
                h_hi, h_lo, wff1_hi, wff1_lo, bff1_l,
                nullptr, ff_hi, ff_lo, NTOK, FFDIM, DMODEL);
        }
        // ff2 (fp32 out)
        {
            dim3 grid(DMODEL / BNT, NTOK / BMT);
            gemm_mma_kernel<false, false><<<grid, 256, GEMM_SMEM_BYTES>>>(
                ff_hi, ff_lo, wff2_hi, wff2_lo, bff2_l,
                t1_buf, nullptr, nullptr, NTOK, DMODEL, FFDIM);
        }
        ln_residual_kernel<<<NTOK, 256>>>(h_buf, t1_buf,
                                          ln2_g + l * DMODEL, ln2_b + l * DMODEL,
                                          h_hi, h_lo);
    }

    pooler_classify_kernel<<<BATCH, 256>>>(h_buf, Wp, bp, Wc, bc, out);
    loss_kernel<<<1, 32>>>(out, label, out + 8);
}